// round 8
// baseline (speedup 1.0000x reference)
#include <cuda_runtime.h>

// y[h] = a0*x[h] + a1*(x[h-1]+x[h+1]) + a2*(x[h-2]+x[h+2]) + a3*(x[h-3]+x[h+3])
// reflect indexing along H. x: (N, C, 256, 256) fp32, alpha: (C, 4) fp32.

#define HH 256
#define WW 256
#define W4 (WW / 4)           // 64 float4 per row
#define PLANES_PER_BLOCK 4    // 4 * 64 = 256 threads

__device__ __forceinline__ int refl(int i) {
    i = (i < 0) ? -i : i;
    return (i < HH) ? i : (2 * HH - 2 - i);
}

__global__ __launch_bounds__(256, 3)   // cap regs ~85 -> 3 CTAs/SM, 24 warps
void hartley_conv_kernel(const float4* __restrict__ x,
                         const float*  __restrict__ alpha,
                         float4* __restrict__ y,
                         int planes, int C)
{
    const int plane = blockIdx.x * PLANES_PER_BLOCK + (threadIdx.x >> 6);
    const int lane  = threadIdx.x & 63;
    if (plane >= planes) return;

    const int c = plane % C;
    const float a0 = alpha[c * 4 + 0];
    const float a1 = alpha[c * 4 + 1];
    const float a2 = alpha[c * 4 + 2];
    const float a3 = alpha[c * 4 + 3];

    const float4* __restrict__ xp = x + (size_t)plane * (HH * W4) + lane;
    float4*       __restrict__ yp = y + (size_t)plane * (HH * W4) + lane;

    // Window: w0..w6 = rows -3..3 (reflected); n0..n1 = rows 4..5.
    float4 w0, w1, w2, w3, w4, w5, w6, n0, n1;
    w3 = xp[0 * W4];
    w2 = xp[1 * W4]; w4 = w2;
    w1 = xp[2 * W4]; w5 = w1;
    w0 = xp[3 * W4]; w6 = w0;
    n0 = xp[4 * W4];
    n1 = xp[5 * W4];

#define TAP(o, p0, p1, p2, p3_, p4, p5, p6)                                             \
    o.x = fmaf(a3, p0.x + p6.x, fmaf(a2, p1.x + p5.x, fmaf(a1, p2.x + p4.x, a0 * p3_.x))); \
    o.y = fmaf(a3, p0.y + p6.y, fmaf(a2, p1.y + p5.y, fmaf(a1, p2.y + p4.y, a0 * p3_.y))); \
    o.z = fmaf(a3, p0.z + p6.z, fmaf(a2, p1.z + p5.z, fmaf(a1, p2.z + p4.z, a0 * p3_.z))); \
    o.w = fmaf(a3, p0.w + p6.w, fmaf(a2, p1.w + p5.w, fmaf(a1, p2.w + p4.w, a0 * p3_.w)))

    #pragma unroll 1
    for (int i = 0; i < HH; i += 2) {
        // Issue next 2 rows (i+6, i+7; reflected near the end) before compute.
        float4 m0 = xp[refl(i + 6) * W4];
        float4 m1 = xp[refl(i + 7) * W4];

        float4 o0, o1;
        TAP(o0, w0, w1, w2, w3, w4, w5, w6);
        TAP(o1, w1, w2, w3, w4, w5, w6, n0);
        yp[(i + 0) * W4] = o0;
        yp[(i + 1) * W4] = o1;

        // Shift window by 2 rows.
        w0 = w2; w1 = w3; w2 = w4; w3 = w5; w4 = w6;
        w5 = n0; w6 = n1;
        n0 = m0; n1 = m1;
    }
#undef TAP
}

extern "C" void kernel_launch(void* const* d_in, const int* in_sizes, int n_in,
                              void* d_out, int out_size)
{
    const float4* x     = (const float4*)d_in[0];
    const float*  alpha = (const float*)d_in[1];
    float4*       y     = (float4*)d_out;

    const int C      = in_sizes[1] / 4;          // alpha is (C, 4)
    const int planes = in_sizes[0] / (HH * WW);  // N * C

    const int grid = (planes + PLANES_PER_BLOCK - 1) / PLANES_PER_BLOCK;
    hartley_conv_kernel<<<grid, 256>>>(x, alpha, y, planes, C);
}

// round 9
// speedup vs baseline: 1.3046x; 1.3046x over previous
#include <cuda_runtime.h>

// y[h] = a0*x[h] + a1*(x[h-1]+x[h+1]) + a2*(x[h-2]+x[h+2]) + a3*(x[h-3]+x[h+3])
// reflect indexing along H. x: (N, C, 256, 256) fp32, alpha: (C, 4) fp32.

#define HH 256
#define WW 256
#define W4 (WW / 4)           // 64 float4 per row
#define PLANES_PER_BLOCK 4    // 4 * 64 = 256 threads

__device__ __forceinline__ int refl(int i) {
    i = (i < 0) ? -i : i;
    return (i < HH) ? i : (2 * HH - 2 - i);
}

__global__ __launch_bounds__(256, 2)
void hartley_conv_kernel(const float4* __restrict__ x,
                         const float*  __restrict__ alpha,
                         float4* __restrict__ y,
                         int planes, int C)
{
    const int plane = blockIdx.x * PLANES_PER_BLOCK + (threadIdx.x >> 6);
    const int lane  = threadIdx.x & 63;
    if (plane >= planes) return;

    const int c = plane % C;
    const float a0 = alpha[c * 4 + 0];
    const float a1 = alpha[c * 4 + 1];
    const float a2 = alpha[c * 4 + 2];
    const float a3 = alpha[c * 4 + 3];

    const float4* __restrict__ xp = x + (size_t)plane * (HH * W4) + lane;
    float4*       __restrict__ yp = y + (size_t)plane * (HH * W4) + lane;

    // Invariant at top of iter i:
    //   w0..w6 = rows i-3 .. i+3 (reflected at start)
    //   n0..n7 = rows i+4 .. i+11
    float4 w0, w1, w2, w3, w4, w5, w6;
    float4 n0, n1, n2, n3, n4, n5, n6, n7;
    w3 = xp[0 * W4];
    w2 = xp[1 * W4]; w4 = w2;
    w1 = xp[2 * W4]; w5 = w1;
    w0 = xp[3 * W4]; w6 = w0;
    n0 = xp[4 * W4];
    n1 = xp[5 * W4];
    n2 = xp[6 * W4];
    n3 = xp[7 * W4];
    n4 = xp[8 * W4];
    n5 = xp[9 * W4];
    n6 = xp[10 * W4];
    n7 = xp[11 * W4];

#define TAP(o, p0, p1, p2, p3_, p4, p5, p6)                                                \
    o.x = fmaf(a3, p0.x + p6.x, fmaf(a2, p1.x + p5.x, fmaf(a1, p2.x + p4.x, a0 * p3_.x))); \
    o.y = fmaf(a3, p0.y + p6.y, fmaf(a2, p1.y + p5.y, fmaf(a1, p2.y + p4.y, a0 * p3_.y))); \
    o.z = fmaf(a3, p0.z + p6.z, fmaf(a2, p1.z + p5.z, fmaf(a1, p2.z + p4.z, a0 * p3_.z))); \
    o.w = fmaf(a3, p0.w + p6.w, fmaf(a2, p1.w + p5.w, fmaf(a1, p2.w + p4.w, a0 * p3_.w)))

    #pragma unroll 1
    for (int i = 0; i < HH; i += 8) {
        // Issue next batch (rows i+12 .. i+19, reflected near the end) FIRST:
        // 8 independent unconditional loads in flight during compute below.
        float4 m0 = xp[refl(i + 12) * W4];
        float4 m1 = xp[refl(i + 13) * W4];
        float4 m2 = xp[refl(i + 14) * W4];
        float4 m3 = xp[refl(i + 15) * W4];
        float4 m4 = xp[refl(i + 16) * W4];
        float4 m5 = xp[refl(i + 17) * W4];
        float4 m6 = xp[refl(i + 18) * W4];
        float4 m7 = xp[refl(i + 19) * W4];

        // Outputs i..i+7 use only data loaded >= 1 iteration ago.
        float4 o;
        TAP(o, w0, w1, w2, w3, w4, w5, w6); yp[(i + 0) * W4] = o;
        TAP(o, w1, w2, w3, w4, w5, w6, n0); yp[(i + 1) * W4] = o;
        TAP(o, w2, w3, w4, w5, w6, n0, n1); yp[(i + 2) * W4] = o;
        TAP(o, w3, w4, w5, w6, n0, n1, n2); yp[(i + 3) * W4] = o;
        TAP(o, w4, w5, w6, n0, n1, n2, n3); yp[(i + 4) * W4] = o;
        TAP(o, w5, w6, n0, n1, n2, n3, n4); yp[(i + 5) * W4] = o;
        TAP(o, w6, n0, n1, n2, n3, n4, n5); yp[(i + 6) * W4] = o;
        TAP(o, n0, n1, n2, n3, n4, n5, n6); yp[(i + 7) * W4] = o;

        // Shift window by 8 rows: new rows i+5..i+11 = n1..n7, next = m.
        w0 = n1; w1 = n2; w2 = n3; w3 = n4; w4 = n5; w5 = n6; w6 = n7;
        n0 = m0; n1 = m1; n2 = m2; n3 = m3; n4 = m4; n5 = m5; n6 = m6; n7 = m7;
    }
#undef TAP
}

extern "C" void kernel_launch(void* const* d_in, const int* in_sizes, int n_in,
                              void* d_out, int out_size)
{
    const float4* x     = (const float4*)d_in[0];
    const float*  alpha = (const float*)d_in[1];
    float4*       y     = (float4*)d_out;

    const int C      = in_sizes[1] / 4;          // alpha is (C, 4)
    const int planes = in_sizes[0] / (HH * WW);  // N * C

    const int grid = (planes + PLANES_PER_BLOCK - 1) / PLANES_PER_BLOCK;
    hartley_conv_kernel<<<grid, 256>>>(x, alpha, y, planes, C);
}

// round 11
// speedup vs baseline: 1.3711x; 1.0510x over previous
#include <cuda_runtime.h>

// y[h] = a0*x[h] + a1*(x[h-1]+x[h+1]) + a2*(x[h-2]+x[h+2]) + a3*(x[h-3]+x[h+3])
// reflect indexing along H. x: (N, C, 256, 256) fp32, alpha: (C, 4) fp32.

#define HH 256
#define WW 256
#define W4 (WW / 4)           // 64 float4 per row
#define PLANES_PER_BLOCK 4    // 4 * 64 = 256 threads

__device__ __forceinline__ int refl(int i) {
    i = (i < 0) ? -i : i;
    return (i < HH) ? i : (2 * HH - 2 - i);
}

__global__ __launch_bounds__(256, 2)
void hartley_conv_kernel(const float4* __restrict__ x,
                         const float*  __restrict__ alpha,
                         float4* __restrict__ y,
                         int planes, int C)
{
    const int plane = blockIdx.x * PLANES_PER_BLOCK + (threadIdx.x >> 6);
    const int lane  = threadIdx.x & 63;
    if (plane >= planes) return;

    const int c = plane % C;
    const float a0 = alpha[c * 4 + 0];
    const float a1 = alpha[c * 4 + 1];
    const float a2 = alpha[c * 4 + 2];
    const float a3 = alpha[c * 4 + 3];

    const float4* __restrict__ xp = x + (size_t)plane * (HH * W4) + lane;
    float4*       __restrict__ yp = y + (size_t)plane * (HH * W4) + lane;

    // Invariant at top of iter i:
    //   w0..w6 = rows i-3 .. i+3 (reflected at start)
    //   n0..n7 = rows i+4 .. i+11
    float4 w0, w1, w2, w3, w4, w5, w6;
    float4 n0, n1, n2, n3, n4, n5, n6, n7;
    w3 = __ldcs(xp + 0 * W4);
    w2 = __ldcs(xp + 1 * W4); w4 = w2;
    w1 = __ldcs(xp + 2 * W4); w5 = w1;
    w0 = __ldcs(xp + 3 * W4); w6 = w0;
    n0 = __ldcs(xp + 4 * W4);
    n1 = __ldcs(xp + 5 * W4);
    n2 = __ldcs(xp + 6 * W4);
    n3 = __ldcs(xp + 7 * W4);
    n4 = __ldcs(xp + 8 * W4);
    n5 = __ldcs(xp + 9 * W4);
    n6 = __ldcs(xp + 10 * W4);
    n7 = __ldcs(xp + 11 * W4);

#define TAP(o, p0, p1, p2, p3_, p4, p5, p6)                                                \
    o.x = fmaf(a3, p0.x + p6.x, fmaf(a2, p1.x + p5.x, fmaf(a1, p2.x + p4.x, a0 * p3_.x))); \
    o.y = fmaf(a3, p0.y + p6.y, fmaf(a2, p1.y + p5.y, fmaf(a1, p2.y + p4.y, a0 * p3_.y))); \
    o.z = fmaf(a3, p0.z + p6.z, fmaf(a2, p1.z + p5.z, fmaf(a1, p2.z + p4.z, a0 * p3_.z))); \
    o.w = fmaf(a3, p0.w + p6.w, fmaf(a2, p1.w + p5.w, fmaf(a1, p2.w + p4.w, a0 * p3_.w)))

    #pragma unroll 1
    for (int i = 0; i < HH; i += 8) {
        // First half-batch of next-iteration rows (i+12..i+15).
        float4 m0 = __ldcs(xp + refl(i + 12) * W4);
        float4 m1 = __ldcs(xp + refl(i + 13) * W4);
        float4 m2 = __ldcs(xp + refl(i + 14) * W4);
        float4 m3 = __ldcs(xp + refl(i + 15) * W4);

        // Rows i..i+3 (consume w0..w3; afterwards w0..w3 are dead).
        float4 o;
        TAP(o, w0, w1, w2, w3, w4, w5, w6); __stcs(yp + (i + 0) * W4, o);
        TAP(o, w1, w2, w3, w4, w5, w6, n0); __stcs(yp + (i + 1) * W4, o);
        TAP(o, w2, w3, w4, w5, w6, n0, n1); __stcs(yp + (i + 2) * W4, o);
        TAP(o, w3, w4, w5, w6, n0, n1, n2); __stcs(yp + (i + 3) * W4, o);

        // Second half-batch (i+16..i+19) — issued after w0..w3 freed,
        // keeping peak live registers at ~19 float4 (no spill).
        float4 m4 = __ldcs(xp + refl(i + 16) * W4);
        float4 m5 = __ldcs(xp + refl(i + 17) * W4);
        float4 m6 = __ldcs(xp + refl(i + 18) * W4);
        float4 m7 = __ldcs(xp + refl(i + 19) * W4);

        // Rows i+4..i+7.
        TAP(o, w4, w5, w6, n0, n1, n2, n3); __stcs(yp + (i + 4) * W4, o);
        TAP(o, w5, w6, n0, n1, n2, n3, n4); __stcs(yp + (i + 5) * W4, o);
        TAP(o, w6, n0, n1, n2, n3, n4, n5); __stcs(yp + (i + 6) * W4, o);
        TAP(o, n0, n1, n2, n3, n4, n5, n6); __stcs(yp + (i + 7) * W4, o);

        // Shift window by 8 rows.
        w0 = n1; w1 = n2; w2 = n3; w3 = n4; w4 = n5; w5 = n6; w6 = n7;
        n0 = m0; n1 = m1; n2 = m2; n3 = m3; n4 = m4; n5 = m5; n6 = m6; n7 = m7;
    }
#undef TAP
}

extern "C" void kernel_launch(void* const* d_in, const int* in_sizes, int n_in,
                              void* d_out, int out_size)
{
    const float4* x     = (const float4*)d_in[0];
    const float*  alpha = (const float*)d_in[1];
    float4*       y     = (float4*)d_out;

    const int C      = in_sizes[1] / 4;          // alpha is (C, 4)
    const int planes = in_sizes[0] / (HH * WW);  // N * C

    const int grid = (planes + PLANES_PER_BLOCK - 1) / PLANES_PER_BLOCK;
    hartley_conv_kernel<<<grid, 256>>>(x, alpha, y, planes, C);
}